// round 13
// baseline (speedup 1.0000x reference)
#include <cuda_runtime.h>
#include <math.h>

#define MAXN 20000
#define MAXE 320000
#define MAXET (MAXE + MAXN)
#define H1 8
#define CH1 32
#define F1 256
#define F0 128
#define F2 64

// ---------------------------------------------------------------------------
// Scratch
// ---------------------------------------------------------------------------
__device__ float g_xl1[MAXN * F1];
__device__ float g_xr1[MAXN * F1];
__device__ float g_h1 [MAXN * F1];
__device__ float g_xl2[MAXN * F2];
__device__ float g_xr2[MAXN * F2];
__device__ float g_h2 [MAXN * F2];

__device__ int g_deg[MAXN];
__device__ int g_rowptr[MAXN + 1];
__device__ int g_cursor[MAXN];
__device__ int g_csrc[MAXET];
__device__ int g_bsum[256];

__device__ float g_fsum[F2];
__device__ float g_fsq [F2];

// ---------------------------------------------------------------------------
// Helpers
// ---------------------------------------------------------------------------
__device__ __forceinline__ float warpSum(float v) {
    #pragma unroll
    for (int o = 16; o > 0; o >>= 1) v += __shfl_xor_sync(0xFFFFFFFFu, v, o);
    return v;
}
__device__ __forceinline__ float warpMax(float v) {
    #pragma unroll
    for (int o = 16; o > 0; o >>= 1) v = fmaxf(v, __shfl_xor_sync(0xFFFFFFFFu, v, o));
    return v;
}
__device__ __forceinline__ float f2tf32f(float x) {
    unsigned u;
    asm("cvt.rna.tf32.f32 %0, %1;" : "=r"(u) : "f"(x));
    return __uint_as_float(u);
}
__device__ __forceinline__ float leaky(float v) { return fmaxf(v, 0.2f * v); }

// ---------------------------------------------------------------------------
// CSR build (side stream, overlapped with layer-1 GEMM)
// ---------------------------------------------------------------------------
__global__ void zero_deg_kernel(int nN) {
    int i = blockIdx.x * blockDim.x + threadIdx.x;
    if (i < nN) g_deg[i] = 0;
    if (i < F2) { g_fsum[i] = 0.f; g_fsq[i] = 0.f; }
}

__global__ void hist_kernel(const int* __restrict__ dst, int nE, int nET) {
    int i = blockIdx.x * blockDim.x + threadIdx.x;
    if (i >= nET) return;
    int d = (i < nE) ? dst[i] : i - nE;
    atomicAdd(&g_deg[d], 1);
}

// Coalesced 2-phase scan.
// Phase 1: per-256-block sums.
__global__ void scan1_kernel(int nN) {
    int i = blockIdx.x * 256 + threadIdx.x;
    int v = (i < nN) ? g_deg[i] : 0;
    int lane = threadIdx.x & 31, w = threadIdx.x >> 5;
    #pragma unroll
    for (int o = 16; o > 0; o >>= 1) v += __shfl_xor_sync(0xFFFFFFFFu, v, o);
    __shared__ int ws[8];
    if (lane == 0) ws[w] = v;
    __syncthreads();
    if (threadIdx.x == 0) {
        int t = 0;
        #pragma unroll
        for (int j = 0; j < 8; j++) t += ws[j];
        g_bsum[blockIdx.x] = t;
    }
}

// Phase 2: each block redundantly computes its own offset from bsum, then
// does a block-local exclusive scan. (scan2 folded in — one less launch.)
__global__ void scan3_kernel(int nb, int nN) {
    int tid = threadIdx.x;
    int bid = blockIdx.x;
    int lane = tid & 31, w = tid >> 5;
    __shared__ int wsA[8], wsB[8];

    // block offset = sum_{j < bid} bsum[j]
    int part = (tid < nb && tid < bid) ? g_bsum[tid] : 0;
    #pragma unroll
    for (int o = 16; o > 0; o >>= 1) part += __shfl_xor_sync(0xFFFFFFFFu, part, o);
    if (lane == 0) wsA[w] = part;
    __syncthreads();
    int boff = 0;
    #pragma unroll
    for (int j = 0; j < 8; j++) boff += wsA[j];

    // block-local exclusive scan
    int i = bid * 256 + tid;
    int v = (i < nN) ? g_deg[i] : 0;
    int x = v;
    #pragma unroll
    for (int o = 1; o < 32; o <<= 1) {
        int t = __shfl_up_sync(0xFFFFFFFFu, x, o);
        if (lane >= o) x += t;
    }
    if (lane == 31) wsB[w] = x;
    __syncthreads();
    int woff = 0;
    for (int j = 0; j < w; j++) woff += wsB[j];
    int excl = x - v + woff + boff;
    if (i < nN) { g_rowptr[i] = excl; g_cursor[i] = excl; }
    if (i == nN - 1) g_rowptr[nN] = excl + v;
}

__global__ void scatter_kernel(const int* __restrict__ src,
                               const int* __restrict__ dst, int nE, int nET) {
    int i = blockIdx.x * blockDim.x + threadIdx.x;
    if (i >= nET) return;
    int s, d;
    if (i < nE) { s = src[i]; d = dst[i]; } else { s = d = i - nE; }
    int slot = atomicAdd(&g_cursor[d], 1);
    g_csrc[slot] = s;
}

// ---------------------------------------------------------------------------
// Pipelined TF32 GEMM: BM=128, BN=64, BK=16, 256 threads (8 warps, 4x2).
// ---------------------------------------------------------------------------
#define PADA 20
#define PADB 72
__global__ void __launch_bounds__(256, 2)
mma_gemm2_kernel(const float* __restrict__ Amat,
                 const float* __restrict__ Bl,
                 const float* __restrict__ Br,
                 float* __restrict__ outL,
                 float* __restrict__ outR,
                 int Mdim, int Kdim, int Ndim) {
    const float* Bmat = blockIdx.z ? Br : Bl;
    float*       Cmat = blockIdx.z ? outR : outL;
    __shared__ __align__(16) float As[2][128][PADA];
    __shared__ __align__(16) float Bs[2][16][PADB];
    int tid = threadIdx.x;
    int lane = tid & 31, warp = tid >> 5;
    int wm = warp >> 1, wn = warp & 1;
    int g = lane >> 2, tg = lane & 3;
    int row0 = blockIdx.y * 128, col0 = blockIdx.x * 64;

    int ar0 = tid >> 2, ac = (tid & 3) * 4;
    int br = tid >> 4, bc = (tid & 15) * 4;

    float4 ra[2], rb;

    float acc[2][4][4];
    #pragma unroll
    for (int i = 0; i < 2; i++)
        #pragma unroll
        for (int j = 0; j < 4; j++)
            #pragma unroll
            for (int k = 0; k < 4; k++) acc[i][j][k] = 0.f;

    int nit = Kdim / 16;

    #pragma unroll
    for (int i = 0; i < 2; i++) {
        int gr = row0 + ar0 + i * 64;
        ra[i] = (gr < Mdim) ? *(const float4*)&Amat[(size_t)gr * Kdim + ac]
                            : make_float4(0.f, 0.f, 0.f, 0.f);
    }
    rb = *(const float4*)&Bmat[(size_t)br * Ndim + col0 + bc];
    #pragma unroll
    for (int i = 0; i < 2; i++) {
        int r = ar0 + i * 64;
        As[0][r][ac + 0] = f2tf32f(ra[i].x);
        As[0][r][ac + 1] = f2tf32f(ra[i].y);
        As[0][r][ac + 2] = f2tf32f(ra[i].z);
        As[0][r][ac + 3] = f2tf32f(ra[i].w);
    }
    Bs[0][br][bc + 0] = f2tf32f(rb.x);
    Bs[0][br][bc + 1] = f2tf32f(rb.y);
    Bs[0][br][bc + 2] = f2tf32f(rb.z);
    Bs[0][br][bc + 3] = f2tf32f(rb.w);
    __syncthreads();

    for (int it = 0; it < nit; it++) {
        int k0n = (it + 1) * 16;
        bool more = (it + 1) < nit;
        if (more) {
            #pragma unroll
            for (int i = 0; i < 2; i++) {
                int gr = row0 + ar0 + i * 64;
                ra[i] = (gr < Mdim) ? *(const float4*)&Amat[(size_t)gr * Kdim + k0n + ac]
                                    : make_float4(0.f, 0.f, 0.f, 0.f);
            }
            rb = *(const float4*)&Bmat[(size_t)(k0n + br) * Ndim + col0 + bc];
        }
        int cb = it & 1;
        #pragma unroll
        for (int kk = 0; kk < 16; kk += 8) {
            unsigned a[2][4], b[4][2];
            #pragma unroll
            for (int mt = 0; mt < 2; mt++) {
                int r = wm * 32 + mt * 16;
                a[mt][0] = __float_as_uint(As[cb][r + g][kk + tg]);
                a[mt][1] = __float_as_uint(As[cb][r + g + 8][kk + tg]);
                a[mt][2] = __float_as_uint(As[cb][r + g][kk + tg + 4]);
                a[mt][3] = __float_as_uint(As[cb][r + g + 8][kk + tg + 4]);
            }
            #pragma unroll
            for (int nt = 0; nt < 4; nt++) {
                int c = wn * 32 + nt * 8 + g;
                b[nt][0] = __float_as_uint(Bs[cb][kk + tg][c]);
                b[nt][1] = __float_as_uint(Bs[cb][kk + tg + 4][c]);
            }
            #pragma unroll
            for (int mt = 0; mt < 2; mt++)
                #pragma unroll
                for (int nt = 0; nt < 4; nt++) {
                    asm volatile(
                        "mma.sync.aligned.m16n8k8.row.col.f32.tf32.tf32.f32 "
                        "{%0,%1,%2,%3}, {%4,%5,%6,%7}, {%8,%9}, {%0,%1,%2,%3};\n"
                        : "+f"(acc[mt][nt][0]), "+f"(acc[mt][nt][1]),
                          "+f"(acc[mt][nt][2]), "+f"(acc[mt][nt][3])
                        : "r"(a[mt][0]), "r"(a[mt][1]), "r"(a[mt][2]), "r"(a[mt][3]),
                          "r"(b[nt][0]), "r"(b[nt][1]));
                }
        }
        if (more) {
            __syncthreads();
            int sb = (it + 1) & 1;
            #pragma unroll
            for (int i = 0; i < 2; i++) {
                int r = ar0 + i * 64;
                As[sb][r][ac + 0] = f2tf32f(ra[i].x);
                As[sb][r][ac + 1] = f2tf32f(ra[i].y);
                As[sb][r][ac + 2] = f2tf32f(ra[i].z);
                As[sb][r][ac + 3] = f2tf32f(ra[i].w);
            }
            Bs[sb][br][bc + 0] = f2tf32f(rb.x);
            Bs[sb][br][bc + 1] = f2tf32f(rb.y);
            Bs[sb][br][bc + 2] = f2tf32f(rb.z);
            Bs[sb][br][bc + 3] = f2tf32f(rb.w);
            __syncthreads();
        }
    }
    #pragma unroll
    for (int mt = 0; mt < 2; mt++) {
        int rbase = row0 + wm * 32 + mt * 16;
        #pragma unroll
        for (int nt = 0; nt < 4; nt++) {
            int c = col0 + wn * 32 + nt * 8 + tg * 2;
            int r = rbase + g;
            if (r < Mdim) *(float2*)&Cmat[(size_t)r * Ndim + c] =
                make_float2(acc[mt][nt][0], acc[mt][nt][1]);
            r = rbase + g + 8;
            if (r < Mdim) *(float2*)&Cmat[(size_t)r * Ndim + c] =
                make_float2(acc[mt][nt][2], acc[mt][nt][3]);
        }
    }
}

// ---------------------------------------------------------------------------
// Fused GAT layer 1 — register-only (no shared memory, no syncs).
// ---------------------------------------------------------------------------
__global__ void gat1_node_kernel(const float* __restrict__ att1,
                                 const float* __restrict__ b1) {
    int d = blockIdx.x;
    int h = threadIdx.x >> 5, lane = threadIdx.x & 31;
    int grp = lane & 7, erow = lane >> 3;
    int c4 = grp * 4;

    float4 at4 = *(const float4*)&att1[h * CH1 + c4];
    float4 xr4 = *(const float4*)&g_xr1[d * F1 + h * CH1 + c4];
    const float* xlh = g_xl1 + h * CH1;

    int beg = g_rowptr[d], end = g_rowptr[d + 1];
    float den = 0.f;
    float4 acc = make_float4(0.f, 0.f, 0.f, 0.f);

    for (int t = beg; t < end; t += 32) {
        int n = end - t; if (n > 32) n = 32;
        int idx = t + lane;
        int sidx = g_csrc[(idx < end) ? idx : beg];
        int np = (n + 3) >> 2;

        int se = __shfl_sync(0xFFFFFFFFu, sidx, erow);
        float4 v = *(const float4*)&xlh[(size_t)se * F1 + c4];

        for (int p = 0; p < np; p++) {
            float4 cur = v;
            if (p + 1 < np) {
                int se2 = __shfl_sync(0xFFFFFFFFu, sidx, (p + 1) * 4 + erow);
                v = *(const float4*)&xlh[(size_t)se2 * F1 + c4];
            }
            int e = p * 4 + erow;
            cur.x += xr4.x; cur.y += xr4.y; cur.z += xr4.z; cur.w += xr4.w;
            float pl = at4.x * leaky(cur.x) + at4.y * leaky(cur.y)
                     + at4.z * leaky(cur.z) + at4.w * leaky(cur.w);
            pl += __shfl_xor_sync(0xFFFFFFFFu, pl, 1);
            pl += __shfl_xor_sync(0xFFFFFFFFu, pl, 2);
            pl += __shfl_xor_sync(0xFFFFFFFFu, pl, 4);
            float w = (e < n) ? __expf(pl) : 0.f;
            if (grp == 0) den += w;
            acc.x += w * cur.x; acc.y += w * cur.y;
            acc.z += w * cur.z; acc.w += w * cur.w;
        }
    }

    acc.x += __shfl_xor_sync(0xFFFFFFFFu, acc.x, 8);
    acc.y += __shfl_xor_sync(0xFFFFFFFFu, acc.y, 8);
    acc.z += __shfl_xor_sync(0xFFFFFFFFu, acc.z, 8);
    acc.w += __shfl_xor_sync(0xFFFFFFFFu, acc.w, 8);
    acc.x += __shfl_xor_sync(0xFFFFFFFFu, acc.x, 16);
    acc.y += __shfl_xor_sync(0xFFFFFFFFu, acc.y, 16);
    acc.z += __shfl_xor_sync(0xFFFFFFFFu, acc.z, 16);
    acc.w += __shfl_xor_sync(0xFFFFFFFFu, acc.w, 16);
    den = warpSum(den);

    if (erow == 0) {
        float inv = 1.f / (den + 1e-16f);
        float4 b4 = *(const float4*)&b1[h * CH1 + c4];
        float4 o;
        o.x = (acc.x - den * xr4.x) * inv + b4.x;
        o.y = (acc.y - den * xr4.y) * inv + b4.y;
        o.z = (acc.z - den * xr4.z) * inv + b4.z;
        o.w = (acc.w - den * xr4.w) * inv + b4.w;
        o.x = (o.x > 0.f) ? o.x : (__expf(o.x) - 1.f);
        o.y = (o.y > 0.f) ? o.y : (__expf(o.y) - 1.f);
        o.z = (o.z > 0.f) ? o.z : (__expf(o.z) - 1.f);
        o.w = (o.w > 0.f) ? o.w : (__expf(o.w) - 1.f);
        *(float4*)&g_h1[d * F1 + h * CH1 + c4] = o;
    }
}

// ---------------------------------------------------------------------------
// Fused GAT layer 2 + InstanceNorm stats accumulation.
// Warp per node; grp = lane&15 owns 4 channels; erow = lane>>4 -> 2 edges/pass.
// Per-block smem stat accumulators -> one global atomic set per block.
// ---------------------------------------------------------------------------
__global__ void gat2_node_kernel(const float* __restrict__ att2, int nN) {
    __shared__ float ssum[F2], ssq[F2];
    if (threadIdx.x < F2) { ssum[threadIdx.x] = 0.f; ssq[threadIdx.x] = 0.f; }
    __syncthreads();

    int d = blockIdx.x * 4 + (threadIdx.x >> 5);
    int lane = threadIdx.x & 31;
    int grp = lane & 15, erow = lane >> 4;
    int c4 = grp * 4;

    if (d < nN) {
        float4 at4 = *(const float4*)&att2[c4];
        float4 xr4 = *(const float4*)&g_xr2[d * F2 + c4];

        int beg = g_rowptr[d], end = g_rowptr[d + 1];
        float den = 0.f;
        float4 acc = make_float4(0.f, 0.f, 0.f, 0.f);

        for (int t = beg; t < end; t += 32) {
            int n = end - t; if (n > 32) n = 32;
            int idx = t + lane;
            int sidx = g_csrc[(idx < end) ? idx : beg];
            int np = (n + 1) >> 1;

            int se = __shfl_sync(0xFFFFFFFFu, sidx, erow);
            float4 v = *(const float4*)&g_xl2[(size_t)se * F2 + c4];

            for (int p = 0; p < np; p++) {
                float4 cur = v;
                if (p + 1 < np) {
                    int se2 = __shfl_sync(0xFFFFFFFFu, sidx, (p + 1) * 2 + erow);
                    v = *(const float4*)&g_xl2[(size_t)se2 * F2 + c4];
                }
                int e = p * 2 + erow;
                cur.x += xr4.x; cur.y += xr4.y; cur.z += xr4.z; cur.w += xr4.w;
                float pl = at4.x * leaky(cur.x) + at4.y * leaky(cur.y)
                         + at4.z * leaky(cur.z) + at4.w * leaky(cur.w);
                pl += __shfl_xor_sync(0xFFFFFFFFu, pl, 1);
                pl += __shfl_xor_sync(0xFFFFFFFFu, pl, 2);
                pl += __shfl_xor_sync(0xFFFFFFFFu, pl, 4);
                pl += __shfl_xor_sync(0xFFFFFFFFu, pl, 8);
                float w = (e < n) ? __expf(pl) : 0.f;
                if (grp == 0) den += w;
                acc.x += w * cur.x; acc.y += w * cur.y;
                acc.z += w * cur.z; acc.w += w * cur.w;
            }
        }

        acc.x += __shfl_xor_sync(0xFFFFFFFFu, acc.x, 16);
        acc.y += __shfl_xor_sync(0xFFFFFFFFu, acc.y, 16);
        acc.z += __shfl_xor_sync(0xFFFFFFFFu, acc.z, 16);
        acc.w += __shfl_xor_sync(0xFFFFFFFFu, acc.w, 16);
        den = warpSum(den);

        if (erow == 0) {
            float inv = 1.f / (den + 1e-16f);
            float4 o;
            o.x = (acc.x - den * xr4.x) * inv;
            o.y = (acc.y - den * xr4.y) * inv;
            o.z = (acc.z - den * xr4.z) * inv;
            o.w = (acc.w - den * xr4.w) * inv;
            *(float4*)&g_h2[d * F2 + c4] = o;   // b2 cancels in InstanceNorm
            // per-block stat accumulation (16 lanes hit 16 distinct banks)
            atomicAdd(&ssum[c4 + 0], o.x);
            atomicAdd(&ssum[c4 + 1], o.y);
            atomicAdd(&ssum[c4 + 2], o.z);
            atomicAdd(&ssum[c4 + 3], o.w);
            atomicAdd(&ssq[c4 + 0], o.x * o.x);
            atomicAdd(&ssq[c4 + 1], o.y * o.y);
            atomicAdd(&ssq[c4 + 2], o.z * o.z);
            atomicAdd(&ssq[c4 + 3], o.w * o.w);
        }
    }
    __syncthreads();
    if (threadIdx.x < F2) {
        atomicAdd(&g_fsum[threadIdx.x], ssum[threadIdx.x]);
        atomicAdd(&g_fsq [threadIdx.x], ssq [threadIdx.x]);
    }
}

// ---------------------------------------------------------------------------
// Normalize + log_softmax (mean/rstd computed inline)
// ---------------------------------------------------------------------------
__global__ void finalize_kernel(const float* __restrict__ gamma,
                                const float* __restrict__ beta,
                                float* __restrict__ out, int nN) {
    int node = blockIdx.x * 4 + (threadIdx.x >> 5);
    if (node >= nN) return;
    int lane = threadIdx.x & 31;
    int c0 = lane, c1 = lane + 32;
    float invN = 1.f / (float)nN;
    float mean0 = g_fsum[c0] * invN;
    float mean1 = g_fsum[c1] * invN;
    float var0 = g_fsq[c0] * invN - mean0 * mean0;
    float var1 = g_fsq[c1] * invN - mean1 * mean1;
    float rstd0 = rsqrtf(var0 + 1e-5f);
    float rstd1 = rsqrtf(var1 + 1e-5f);
    float y0 = (g_h2[node * F2 + c0] - mean0) * rstd0 * gamma[c0] + beta[c0];
    float y1 = (g_h2[node * F2 + c1] - mean1) * rstd1 * gamma[c1] + beta[c1];
    out[node * F2 + c0] = y0;
    out[node * F2 + c1] = y1;
    float m = warpMax(fmaxf(y0, y1));
    float ssum = warpSum(expf(y0 - m) + expf(y1 - m));
    float lse = m + logf(ssum);
    float* out2 = out + (size_t)nN * F2;
    out2[node * F2 + c0] = y0 - lse;
    out2[node * F2 + c1] = y1 - lse;
}

// ---------------------------------------------------------------------------
// Launcher — CSR build forked onto side stream, overlapped with layer-1 GEMM
// ---------------------------------------------------------------------------
static cudaStream_t s_side = nullptr;
static cudaEvent_t  s_ev0 = nullptr, s_ev1 = nullptr;

extern "C" void kernel_launch(void* const* d_in, const int* in_sizes, int n_in,
                              void* d_out, int out_size) {
    const float* x     = (const float*)d_in[0];
    const float* Wl1   = (const float*)d_in[1];
    const float* Wr1   = (const float*)d_in[2];
    const float* att1  = (const float*)d_in[3];
    const float* b1    = (const float*)d_in[4];
    const float* Wl2   = (const float*)d_in[5];
    const float* Wr2   = (const float*)d_in[6];
    const float* att2  = (const float*)d_in[7];
    const float* gamma = (const float*)d_in[9];
    const float* beta  = (const float*)d_in[10];
    const int*   ei    = (const int*)d_in[11];

    int nN = in_sizes[0] / F0;
    int nE = in_sizes[11] / 2;
    int nET = nE + nN;
    int nb = (nN + 255) / 256;
    const int* src = ei;
    const int* dst = ei + nE;

    if (s_side == nullptr) {
        cudaStreamCreateWithFlags(&s_side, cudaStreamNonBlocking);
        cudaEventCreateWithFlags(&s_ev0, cudaEventDisableTiming);
        cudaEventCreateWithFlags(&s_ev1, cudaEventDisableTiming);
    }

    float *xl1, *xr1, *h1, *xl2, *xr2;
    cudaGetSymbolAddress((void**)&xl1, g_xl1);
    cudaGetSymbolAddress((void**)&xr1, g_xr1);
    cudaGetSymbolAddress((void**)&h1,  g_h1);
    cudaGetSymbolAddress((void**)&xl2, g_xl2);
    cudaGetSymbolAddress((void**)&xr2, g_xr2);

    // Fork: CSR build on side stream
    cudaEventRecord(s_ev0, 0);
    cudaStreamWaitEvent(s_side, s_ev0, 0);
    zero_deg_kernel<<<(nN + 255) / 256, 256, 0, s_side>>>(nN);
    hist_kernel<<<(nET + 255) / 256, 256, 0, s_side>>>(dst, nE, nET);
    scan1_kernel<<<nb, 256, 0, s_side>>>(nN);
    scan3_kernel<<<nb, 256, 0, s_side>>>(nb, nN);
    scatter_kernel<<<(nET + 255) / 256, 256, 0, s_side>>>(src, dst, nE, nET);
    cudaEventRecord(s_ev1, s_side);

    // Main: layer-1 GEMMs concurrent with CSR
    {
        dim3 grid(F1 / 64, (nN + 127) / 128, 2);
        mma_gemm2_kernel<<<grid, 256>>>(x, Wl1, Wr1, xl1, xr1, nN, F0, F1);
    }
    // Join
    cudaStreamWaitEvent(0, s_ev1, 0);

    gat1_node_kernel<<<nN, 256>>>(att1, b1);

    {
        dim3 grid(F2 / 64, (nN + 127) / 128, 2);
        mma_gemm2_kernel<<<grid, 256>>>(h1, Wl2, Wr2, xl2, xr2, nN, F1, F2);
    }
    gat2_node_kernel<<<(nN + 3) / 4, 128>>>(att2, nN);

    finalize_kernel<<<(nN + 3) / 4, 128>>>(gamma, beta, (float*)d_out, nN);
}

// round 14
// speedup vs baseline: 1.0013x; 1.0013x over previous
#include <cuda_runtime.h>
#include <math.h>

#define MAXN 20000
#define MAXE 320000
#define MAXET (MAXE + MAXN)
#define H1 8
#define CH1 32
#define F1 256
#define F0 128
#define F2 64

// ---------------------------------------------------------------------------
// Scratch
// ---------------------------------------------------------------------------
__device__ float g_xl1[MAXN * F1];
__device__ float g_xr1[MAXN * F1];
__device__ float g_h1 [MAXN * F1];
__device__ float g_xl2[MAXN * F2];
__device__ float g_xr2[MAXN * F2];
__device__ float g_h2 [MAXN * F2];

__device__ int g_deg[MAXN];
__device__ int g_rowptr[MAXN + 1];
__device__ int g_cursor[MAXN];
__device__ int g_csrc[MAXET];
__device__ int g_bsum[256];

__device__ float g_fsum[F2];
__device__ float g_fsq [F2];

// ---------------------------------------------------------------------------
// Helpers
// ---------------------------------------------------------------------------
__device__ __forceinline__ float warpSum(float v) {
    #pragma unroll
    for (int o = 16; o > 0; o >>= 1) v += __shfl_xor_sync(0xFFFFFFFFu, v, o);
    return v;
}
__device__ __forceinline__ float warpMax(float v) {
    #pragma unroll
    for (int o = 16; o > 0; o >>= 1) v = fmaxf(v, __shfl_xor_sync(0xFFFFFFFFu, v, o));
    return v;
}
__device__ __forceinline__ float f2tf32f(float x) {
    unsigned u;
    asm("cvt.rna.tf32.f32 %0, %1;" : "=r"(u) : "f"(x));
    return __uint_as_float(u);
}
__device__ __forceinline__ float leaky(float v) { return fmaxf(v, 0.2f * v); }

// ---------------------------------------------------------------------------
// CSR build (side stream, overlapped with layer-1 GEMM)
// ---------------------------------------------------------------------------
__global__ void zero_deg_kernel(int nN) {
    int i = blockIdx.x * blockDim.x + threadIdx.x;
    if (i < nN) g_deg[i] = 0;
    if (i < F2) { g_fsum[i] = 0.f; g_fsq[i] = 0.f; }
}

__global__ void hist_kernel(const int* __restrict__ dst, int nE, int nET) {
    int i = blockIdx.x * blockDim.x + threadIdx.x;
    if (i >= nET) return;
    int d = (i < nE) ? dst[i] : i - nE;
    atomicAdd(&g_deg[d], 1);
}

// Coalesced 2-phase scan.
// Phase 1: per-256-block sums.
__global__ void scan1_kernel(int nN) {
    int i = blockIdx.x * 256 + threadIdx.x;
    int v = (i < nN) ? g_deg[i] : 0;
    int lane = threadIdx.x & 31, w = threadIdx.x >> 5;
    #pragma unroll
    for (int o = 16; o > 0; o >>= 1) v += __shfl_xor_sync(0xFFFFFFFFu, v, o);
    __shared__ int ws[8];
    if (lane == 0) ws[w] = v;
    __syncthreads();
    if (threadIdx.x == 0) {
        int t = 0;
        #pragma unroll
        for (int j = 0; j < 8; j++) t += ws[j];
        g_bsum[blockIdx.x] = t;
    }
}

// Phase 2: each block redundantly computes its own offset from bsum, then
// does a block-local exclusive scan. (scan2 folded in — one less launch.)
__global__ void scan3_kernel(int nb, int nN) {
    int tid = threadIdx.x;
    int bid = blockIdx.x;
    int lane = tid & 31, w = tid >> 5;
    __shared__ int wsA[8], wsB[8];

    // block offset = sum_{j < bid} bsum[j]
    int part = (tid < nb && tid < bid) ? g_bsum[tid] : 0;
    #pragma unroll
    for (int o = 16; o > 0; o >>= 1) part += __shfl_xor_sync(0xFFFFFFFFu, part, o);
    if (lane == 0) wsA[w] = part;
    __syncthreads();
    int boff = 0;
    #pragma unroll
    for (int j = 0; j < 8; j++) boff += wsA[j];

    // block-local exclusive scan
    int i = bid * 256 + tid;
    int v = (i < nN) ? g_deg[i] : 0;
    int x = v;
    #pragma unroll
    for (int o = 1; o < 32; o <<= 1) {
        int t = __shfl_up_sync(0xFFFFFFFFu, x, o);
        if (lane >= o) x += t;
    }
    if (lane == 31) wsB[w] = x;
    __syncthreads();
    int woff = 0;
    for (int j = 0; j < w; j++) woff += wsB[j];
    int excl = x - v + woff + boff;
    if (i < nN) { g_rowptr[i] = excl; g_cursor[i] = excl; }
    if (i == nN - 1) g_rowptr[nN] = excl + v;
}

__global__ void scatter_kernel(const int* __restrict__ src,
                               const int* __restrict__ dst, int nE, int nET) {
    int i = blockIdx.x * blockDim.x + threadIdx.x;
    if (i >= nET) return;
    int s, d;
    if (i < nE) { s = src[i]; d = dst[i]; } else { s = d = i - nE; }
    int slot = atomicAdd(&g_cursor[d], 1);
    g_csrc[slot] = s;
}

// ---------------------------------------------------------------------------
// Pipelined TF32 GEMM: BM=128, BN=64, BK=16, 256 threads (8 warps, 4x2).
// ---------------------------------------------------------------------------
#define PADA 20
#define PADB 72
__global__ void __launch_bounds__(256, 2)
mma_gemm2_kernel(const float* __restrict__ Amat,
                 const float* __restrict__ Bl,
                 const float* __restrict__ Br,
                 float* __restrict__ outL,
                 float* __restrict__ outR,
                 int Mdim, int Kdim, int Ndim) {
    const float* Bmat = blockIdx.z ? Br : Bl;
    float*       Cmat = blockIdx.z ? outR : outL;
    __shared__ __align__(16) float As[2][128][PADA];
    __shared__ __align__(16) float Bs[2][16][PADB];
    int tid = threadIdx.x;
    int lane = tid & 31, warp = tid >> 5;
    int wm = warp >> 1, wn = warp & 1;
    int g = lane >> 2, tg = lane & 3;
    int row0 = blockIdx.y * 128, col0 = blockIdx.x * 64;

    int ar0 = tid >> 2, ac = (tid & 3) * 4;
    int br = tid >> 4, bc = (tid & 15) * 4;

    float4 ra[2], rb;

    float acc[2][4][4];
    #pragma unroll
    for (int i = 0; i < 2; i++)
        #pragma unroll
        for (int j = 0; j < 4; j++)
            #pragma unroll
            for (int k = 0; k < 4; k++) acc[i][j][k] = 0.f;

    int nit = Kdim / 16;

    #pragma unroll
    for (int i = 0; i < 2; i++) {
        int gr = row0 + ar0 + i * 64;
        ra[i] = (gr < Mdim) ? *(const float4*)&Amat[(size_t)gr * Kdim + ac]
                            : make_float4(0.f, 0.f, 0.f, 0.f);
    }
    rb = *(const float4*)&Bmat[(size_t)br * Ndim + col0 + bc];
    #pragma unroll
    for (int i = 0; i < 2; i++) {
        int r = ar0 + i * 64;
        As[0][r][ac + 0] = f2tf32f(ra[i].x);
        As[0][r][ac + 1] = f2tf32f(ra[i].y);
        As[0][r][ac + 2] = f2tf32f(ra[i].z);
        As[0][r][ac + 3] = f2tf32f(ra[i].w);
    }
    Bs[0][br][bc + 0] = f2tf32f(rb.x);
    Bs[0][br][bc + 1] = f2tf32f(rb.y);
    Bs[0][br][bc + 2] = f2tf32f(rb.z);
    Bs[0][br][bc + 3] = f2tf32f(rb.w);
    __syncthreads();

    for (int it = 0; it < nit; it++) {
        int k0n = (it + 1) * 16;
        bool more = (it + 1) < nit;
        if (more) {
            #pragma unroll
            for (int i = 0; i < 2; i++) {
                int gr = row0 + ar0 + i * 64;
                ra[i] = (gr < Mdim) ? *(const float4*)&Amat[(size_t)gr * Kdim + k0n + ac]
                                    : make_float4(0.f, 0.f, 0.f, 0.f);
            }
            rb = *(const float4*)&Bmat[(size_t)(k0n + br) * Ndim + col0 + bc];
        }
        int cb = it & 1;
        #pragma unroll
        for (int kk = 0; kk < 16; kk += 8) {
            unsigned a[2][4], b[4][2];
            #pragma unroll
            for (int mt = 0; mt < 2; mt++) {
                int r = wm * 32 + mt * 16;
                a[mt][0] = __float_as_uint(As[cb][r + g][kk + tg]);
                a[mt][1] = __float_as_uint(As[cb][r + g + 8][kk + tg]);
                a[mt][2] = __float_as_uint(As[cb][r + g][kk + tg + 4]);
                a[mt][3] = __float_as_uint(As[cb][r + g + 8][kk + tg + 4]);
            }
            #pragma unroll
            for (int nt = 0; nt < 4; nt++) {
                int c = wn * 32 + nt * 8 + g;
                b[nt][0] = __float_as_uint(Bs[cb][kk + tg][c]);
                b[nt][1] = __float_as_uint(Bs[cb][kk + tg + 4][c]);
            }
            #pragma unroll
            for (int mt = 0; mt < 2; mt++)
                #pragma unroll
                for (int nt = 0; nt < 4; nt++) {
                    asm volatile(
                        "mma.sync.aligned.m16n8k8.row.col.f32.tf32.tf32.f32 "
                        "{%0,%1,%2,%3}, {%4,%5,%6,%7}, {%8,%9}, {%0,%1,%2,%3};\n"
                        : "+f"(acc[mt][nt][0]), "+f"(acc[mt][nt][1]),
                          "+f"(acc[mt][nt][2]), "+f"(acc[mt][nt][3])
                        : "r"(a[mt][0]), "r"(a[mt][1]), "r"(a[mt][2]), "r"(a[mt][3]),
                          "r"(b[nt][0]), "r"(b[nt][1]));
                }
        }
        if (more) {
            __syncthreads();
            int sb = (it + 1) & 1;
            #pragma unroll
            for (int i = 0; i < 2; i++) {
                int r = ar0 + i * 64;
                As[sb][r][ac + 0] = f2tf32f(ra[i].x);
                As[sb][r][ac + 1] = f2tf32f(ra[i].y);
                As[sb][r][ac + 2] = f2tf32f(ra[i].z);
                As[sb][r][ac + 3] = f2tf32f(ra[i].w);
            }
            Bs[sb][br][bc + 0] = f2tf32f(rb.x);
            Bs[sb][br][bc + 1] = f2tf32f(rb.y);
            Bs[sb][br][bc + 2] = f2tf32f(rb.z);
            Bs[sb][br][bc + 3] = f2tf32f(rb.w);
            __syncthreads();
        }
    }
    #pragma unroll
    for (int mt = 0; mt < 2; mt++) {
        int rbase = row0 + wm * 32 + mt * 16;
        #pragma unroll
        for (int nt = 0; nt < 4; nt++) {
            int c = col0 + wn * 32 + nt * 8 + tg * 2;
            int r = rbase + g;
            if (r < Mdim) *(float2*)&Cmat[(size_t)r * Ndim + c] =
                make_float2(acc[mt][nt][0], acc[mt][nt][1]);
            r = rbase + g + 8;
            if (r < Mdim) *(float2*)&Cmat[(size_t)r * Ndim + c] =
                make_float2(acc[mt][nt][2], acc[mt][nt][3]);
        }
    }
}

// ---------------------------------------------------------------------------
// Fused GAT layer 1 — register-only (no shared memory, no syncs).
// ---------------------------------------------------------------------------
__global__ void gat1_node_kernel(const float* __restrict__ att1,
                                 const float* __restrict__ b1) {
    int d = blockIdx.x;
    int h = threadIdx.x >> 5, lane = threadIdx.x & 31;
    int grp = lane & 7, erow = lane >> 3;
    int c4 = grp * 4;

    float4 at4 = *(const float4*)&att1[h * CH1 + c4];
    float4 xr4 = *(const float4*)&g_xr1[d * F1 + h * CH1 + c4];
    const float* xlh = g_xl1 + h * CH1;

    int beg = g_rowptr[d], end = g_rowptr[d + 1];
    float den = 0.f;
    float4 acc = make_float4(0.f, 0.f, 0.f, 0.f);

    for (int t = beg; t < end; t += 32) {
        int n = end - t; if (n > 32) n = 32;
        int idx = t + lane;
        int sidx = g_csrc[(idx < end) ? idx : beg];
        int np = (n + 3) >> 2;

        int se = __shfl_sync(0xFFFFFFFFu, sidx, erow);
        float4 v = *(const float4*)&xlh[(size_t)se * F1 + c4];

        for (int p = 0; p < np; p++) {
            float4 cur = v;
            if (p + 1 < np) {
                int se2 = __shfl_sync(0xFFFFFFFFu, sidx, (p + 1) * 4 + erow);
                v = *(const float4*)&xlh[(size_t)se2 * F1 + c4];
            }
            int e = p * 4 + erow;
            cur.x += xr4.x; cur.y += xr4.y; cur.z += xr4.z; cur.w += xr4.w;
            float pl = at4.x * leaky(cur.x) + at4.y * leaky(cur.y)
                     + at4.z * leaky(cur.z) + at4.w * leaky(cur.w);
            pl += __shfl_xor_sync(0xFFFFFFFFu, pl, 1);
            pl += __shfl_xor_sync(0xFFFFFFFFu, pl, 2);
            pl += __shfl_xor_sync(0xFFFFFFFFu, pl, 4);
            float w = (e < n) ? __expf(pl) : 0.f;
            if (grp == 0) den += w;
            acc.x += w * cur.x; acc.y += w * cur.y;
            acc.z += w * cur.z; acc.w += w * cur.w;
        }
    }

    acc.x += __shfl_xor_sync(0xFFFFFFFFu, acc.x, 8);
    acc.y += __shfl_xor_sync(0xFFFFFFFFu, acc.y, 8);
    acc.z += __shfl_xor_sync(0xFFFFFFFFu, acc.z, 8);
    acc.w += __shfl_xor_sync(0xFFFFFFFFu, acc.w, 8);
    acc.x += __shfl_xor_sync(0xFFFFFFFFu, acc.x, 16);
    acc.y += __shfl_xor_sync(0xFFFFFFFFu, acc.y, 16);
    acc.z += __shfl_xor_sync(0xFFFFFFFFu, acc.z, 16);
    acc.w += __shfl_xor_sync(0xFFFFFFFFu, acc.w, 16);
    den = warpSum(den);

    if (erow == 0) {
        float inv = 1.f / (den + 1e-16f);
        float4 b4 = *(const float4*)&b1[h * CH1 + c4];
        float4 o;
        o.x = (acc.x - den * xr4.x) * inv + b4.x;
        o.y = (acc.y - den * xr4.y) * inv + b4.y;
        o.z = (acc.z - den * xr4.z) * inv + b4.z;
        o.w = (acc.w - den * xr4.w) * inv + b4.w;
        o.x = (o.x > 0.f) ? o.x : (__expf(o.x) - 1.f);
        o.y = (o.y > 0.f) ? o.y : (__expf(o.y) - 1.f);
        o.z = (o.z > 0.f) ? o.z : (__expf(o.z) - 1.f);
        o.w = (o.w > 0.f) ? o.w : (__expf(o.w) - 1.f);
        *(float4*)&g_h1[d * F1 + h * CH1 + c4] = o;
    }
}

// ---------------------------------------------------------------------------
// Fused GAT layer 2 + InstanceNorm stats accumulation.
// Warp per node; grp = lane&15 owns 4 channels; erow = lane>>4 -> 2 edges/pass.
// Per-block smem stat accumulators -> one global atomic set per block.
// ---------------------------------------------------------------------------
__global__ void gat2_node_kernel(const float* __restrict__ att2, int nN) {
    __shared__ float ssum[F2], ssq[F2];
    if (threadIdx.x < F2) { ssum[threadIdx.x] = 0.f; ssq[threadIdx.x] = 0.f; }
    __syncthreads();

    int d = blockIdx.x * 4 + (threadIdx.x >> 5);
    int lane = threadIdx.x & 31;
    int grp = lane & 15, erow = lane >> 4;
    int c4 = grp * 4;

    if (d < nN) {
        float4 at4 = *(const float4*)&att2[c4];
        float4 xr4 = *(const float4*)&g_xr2[d * F2 + c4];

        int beg = g_rowptr[d], end = g_rowptr[d + 1];
        float den = 0.f;
        float4 acc = make_float4(0.f, 0.f, 0.f, 0.f);

        for (int t = beg; t < end; t += 32) {
            int n = end - t; if (n > 32) n = 32;
            int idx = t + lane;
            int sidx = g_csrc[(idx < end) ? idx : beg];
            int np = (n + 1) >> 1;

            int se = __shfl_sync(0xFFFFFFFFu, sidx, erow);
            float4 v = *(const float4*)&g_xl2[(size_t)se * F2 + c4];

            for (int p = 0; p < np; p++) {
                float4 cur = v;
                if (p + 1 < np) {
                    int se2 = __shfl_sync(0xFFFFFFFFu, sidx, (p + 1) * 2 + erow);
                    v = *(const float4*)&g_xl2[(size_t)se2 * F2 + c4];
                }
                int e = p * 2 + erow;
                cur.x += xr4.x; cur.y += xr4.y; cur.z += xr4.z; cur.w += xr4.w;
                float pl = at4.x * leaky(cur.x) + at4.y * leaky(cur.y)
                         + at4.z * leaky(cur.z) + at4.w * leaky(cur.w);
                pl += __shfl_xor_sync(0xFFFFFFFFu, pl, 1);
                pl += __shfl_xor_sync(0xFFFFFFFFu, pl, 2);
                pl += __shfl_xor_sync(0xFFFFFFFFu, pl, 4);
                pl += __shfl_xor_sync(0xFFFFFFFFu, pl, 8);
                float w = (e < n) ? __expf(pl) : 0.f;
                if (grp == 0) den += w;
                acc.x += w * cur.x; acc.y += w * cur.y;
                acc.z += w * cur.z; acc.w += w * cur.w;
            }
        }

        acc.x += __shfl_xor_sync(0xFFFFFFFFu, acc.x, 16);
        acc.y += __shfl_xor_sync(0xFFFFFFFFu, acc.y, 16);
        acc.z += __shfl_xor_sync(0xFFFFFFFFu, acc.z, 16);
        acc.w += __shfl_xor_sync(0xFFFFFFFFu, acc.w, 16);
        den = warpSum(den);

        if (erow == 0) {
            float inv = 1.f / (den + 1e-16f);
            float4 o;
            o.x = (acc.x - den * xr4.x) * inv;
            o.y = (acc.y - den * xr4.y) * inv;
            o.z = (acc.z - den * xr4.z) * inv;
            o.w = (acc.w - den * xr4.w) * inv;
            *(float4*)&g_h2[d * F2 + c4] = o;   // b2 cancels in InstanceNorm
            // per-block stat accumulation (16 lanes hit 16 distinct banks)
            atomicAdd(&ssum[c4 + 0], o.x);
            atomicAdd(&ssum[c4 + 1], o.y);
            atomicAdd(&ssum[c4 + 2], o.z);
            atomicAdd(&ssum[c4 + 3], o.w);
            atomicAdd(&ssq[c4 + 0], o.x * o.x);
            atomicAdd(&ssq[c4 + 1], o.y * o.y);
            atomicAdd(&ssq[c4 + 2], o.z * o.z);
            atomicAdd(&ssq[c4 + 3], o.w * o.w);
        }
    }
    __syncthreads();
    if (threadIdx.x < F2) {
        atomicAdd(&g_fsum[threadIdx.x], ssum[threadIdx.x]);
        atomicAdd(&g_fsq [threadIdx.x], ssq [threadIdx.x]);
    }
}

// ---------------------------------------------------------------------------
// Normalize + log_softmax (mean/rstd computed inline)
// ---------------------------------------------------------------------------
__global__ void finalize_kernel(const float* __restrict__ gamma,
                                const float* __restrict__ beta,
                                float* __restrict__ out, int nN) {
    int node = blockIdx.x * 4 + (threadIdx.x >> 5);
    if (node >= nN) return;
    int lane = threadIdx.x & 31;
    int c0 = lane, c1 = lane + 32;
    float invN = 1.f / (float)nN;
    float mean0 = g_fsum[c0] * invN;
    float mean1 = g_fsum[c1] * invN;
    float var0 = g_fsq[c0] * invN - mean0 * mean0;
    float var1 = g_fsq[c1] * invN - mean1 * mean1;
    float rstd0 = rsqrtf(var0 + 1e-5f);
    float rstd1 = rsqrtf(var1 + 1e-5f);
    float y0 = (g_h2[node * F2 + c0] - mean0) * rstd0 * gamma[c0] + beta[c0];
    float y1 = (g_h2[node * F2 + c1] - mean1) * rstd1 * gamma[c1] + beta[c1];
    out[node * F2 + c0] = y0;
    out[node * F2 + c1] = y1;
    float m = warpMax(fmaxf(y0, y1));
    float ssum = warpSum(expf(y0 - m) + expf(y1 - m));
    float lse = m + logf(ssum);
    float* out2 = out + (size_t)nN * F2;
    out2[node * F2 + c0] = y0 - lse;
    out2[node * F2 + c1] = y1 - lse;
}

// ---------------------------------------------------------------------------
// Launcher — CSR build forked onto side stream, overlapped with layer-1 GEMM
// ---------------------------------------------------------------------------
static cudaStream_t s_side = nullptr;
static cudaEvent_t  s_ev0 = nullptr, s_ev1 = nullptr;

extern "C" void kernel_launch(void* const* d_in, const int* in_sizes, int n_in,
                              void* d_out, int out_size) {
    const float* x     = (const float*)d_in[0];
    const float* Wl1   = (const float*)d_in[1];
    const float* Wr1   = (const float*)d_in[2];
    const float* att1  = (const float*)d_in[3];
    const float* b1    = (const float*)d_in[4];
    const float* Wl2   = (const float*)d_in[5];
    const float* Wr2   = (const float*)d_in[6];
    const float* att2  = (const float*)d_in[7];
    const float* gamma = (const float*)d_in[9];
    const float* beta  = (const float*)d_in[10];
    const int*   ei    = (const int*)d_in[11];

    int nN = in_sizes[0] / F0;
    int nE = in_sizes[11] / 2;
    int nET = nE + nN;
    int nb = (nN + 255) / 256;
    const int* src = ei;
    const int* dst = ei + nE;

    if (s_side == nullptr) {
        cudaStreamCreateWithFlags(&s_side, cudaStreamNonBlocking);
        cudaEventCreateWithFlags(&s_ev0, cudaEventDisableTiming);
        cudaEventCreateWithFlags(&s_ev1, cudaEventDisableTiming);
    }

    float *xl1, *xr1, *h1, *xl2, *xr2;
    cudaGetSymbolAddress((void**)&xl1, g_xl1);
    cudaGetSymbolAddress((void**)&xr1, g_xr1);
    cudaGetSymbolAddress((void**)&h1,  g_h1);
    cudaGetSymbolAddress((void**)&xl2, g_xl2);
    cudaGetSymbolAddress((void**)&xr2, g_xr2);

    // Fork: CSR build on side stream
    cudaEventRecord(s_ev0, 0);
    cudaStreamWaitEvent(s_side, s_ev0, 0);
    zero_deg_kernel<<<(nN + 255) / 256, 256, 0, s_side>>>(nN);
    hist_kernel<<<(nET + 255) / 256, 256, 0, s_side>>>(dst, nE, nET);
    scan1_kernel<<<nb, 256, 0, s_side>>>(nN);
    scan3_kernel<<<nb, 256, 0, s_side>>>(nb, nN);
    scatter_kernel<<<(nET + 255) / 256, 256, 0, s_side>>>(src, dst, nE, nET);
    cudaEventRecord(s_ev1, s_side);

    // Main: layer-1 GEMMs concurrent with CSR
    {
        dim3 grid(F1 / 64, (nN + 127) / 128, 2);
        mma_gemm2_kernel<<<grid, 256>>>(x, Wl1, Wr1, xl1, xr1, nN, F0, F1);
    }
    // Join
    cudaStreamWaitEvent(0, s_ev1, 0);

    gat1_node_kernel<<<nN, 256>>>(att1, b1);

    {
        dim3 grid(F2 / 64, (nN + 127) / 128, 2);
        mma_gemm2_kernel<<<grid, 256>>>(h1, Wl2, Wr2, xl2, xr2, nN, F1, F2);
    }
    gat2_node_kernel<<<(nN + 3) / 4, 128>>>(att2, nN);

    finalize_kernel<<<(nN + 3) / 4, 128>>>(gamma, beta, (float*)d_out, nN);
}